// round 1
// baseline (speedup 1.0000x reference)
#include <cuda_runtime.h>

#define DD 64
#define H_ 256
#define W_ 512
#define HW_ (H_ * W_)
#define B_ 8
#define NPIX (B_ * HW_)
#define VEC 4
#define TPB 256
#define NTHREADS (NPIX / VEC)
#define NBLOCKS (NTHREADS / TPB)

__device__ double g_sum;
__device__ unsigned long long g_cnt;

__global__ void sce_init() {
    g_sum = 0.0;
    g_cnt = 0ull;
}

__global__ __launch_bounds__(TPB) void sce_main(const float* __restrict__ sim,
                                                const float* __restrict__ gt) {
    int t = blockIdx.x * TPB + threadIdx.x;
    long long base = (long long)t * VEC;
    int b = (int)(base / HW_);
    int hw = (int)(base - (long long)b * HW_);

    float4 g4 = *reinterpret_cast<const float4*>(gt + base);
    float gts[VEC] = {g4.x, g4.y, g4.z, g4.w};

    float esum[VEC], pts[VEC], ptn[VEC];
#pragma unroll
    for (int j = 0; j < VEC; ++j) { esum[j] = 0.f; pts[j] = 0.f; ptn[j] = 0.f; }

    const float* sbase = sim + (long long)b * DD * HW_ + hw;

#pragma unroll 4
    for (int d = 0; d < DD; ++d) {
        float4 s4 = *reinterpret_cast<const float4*>(sbase + (long long)d * HW_);
        float sv[VEC] = {s4.x, s4.y, s4.z, s4.w};
        float dd = 2.0f * (float)d;
#pragma unroll
        for (int j = 0; j < VEC; ++j) {
            float s = sv[j];
            esum[j] += __expf(s);
            float p = __expf(-fabsf(gts[j] - dd));
            pts[j] = fmaf(p, s, pts[j]);
            ptn[j] += p;
        }
    }

    double lsum = 0.0;
    unsigned int lcnt = 0u;
#pragma unroll
    for (int j = 0; j < VEC; ++j) {
        if (isfinite(gts[j])) {
            // entropy = lse - sum(Pt*s)/sum(Pt); lse = log(sum exp(s)) (no shift needed, |s|<~7)
            float ent = __logf(esum[j]) - pts[j] / ptn[j];
            lsum += (double)ent;
            lcnt++;
        }
    }

    // Warp reduction
    const unsigned mask = 0xffffffffu;
#pragma unroll
    for (int o = 16; o > 0; o >>= 1) {
        lsum += __shfl_down_sync(mask, lsum, o);
        lcnt += __shfl_down_sync(mask, lcnt, o);
    }

    __shared__ double ssum[TPB / 32];
    __shared__ unsigned int scnt[TPB / 32];
    int lane = threadIdx.x & 31;
    int warp = threadIdx.x >> 5;
    if (lane == 0) { ssum[warp] = lsum; scnt[warp] = lcnt; }
    __syncthreads();

    if (warp == 0) {
        lsum = (lane < TPB / 32) ? ssum[lane] : 0.0;
        lcnt = (lane < TPB / 32) ? scnt[lane] : 0u;
#pragma unroll
        for (int o = 4; o > 0; o >>= 1) {
            lsum += __shfl_down_sync(mask, lsum, o);
            lcnt += __shfl_down_sync(mask, lcnt, o);
        }
        if (lane == 0) {
            atomicAdd(&g_sum, lsum);
            atomicAdd(&g_cnt, (unsigned long long)lcnt);
        }
    }
}

__global__ void sce_fin(float* out) {
    out[0] = (float)(g_sum / (double)g_cnt);
}

extern "C" void kernel_launch(void* const* d_in, const int* in_sizes, int n_in,
                              void* d_out, int out_size) {
    const float* sim = (const float*)d_in[0];
    const float* gt  = (const float*)d_in[1];
    float* out = (float*)d_out;

    sce_init<<<1, 1>>>();
    sce_main<<<NBLOCKS, TPB>>>(sim, gt);
    sce_fin<<<1, 1>>>(out);
}

// round 2
// speedup vs baseline: 1.0258x; 1.0258x over previous
#include <cuda_runtime.h>

#define DD 64
#define H_ 256
#define W_ 512
#define HW_ (H_ * W_)
#define B_ 8
#define NPIX (B_ * HW_)
#define VEC 4
#define TPB 256
#define NTHREADS (NPIX / VEC)
#define NBLOCKS (NTHREADS / TPB)   // 1024

__device__ double g_part[NBLOCKS];
__device__ unsigned int g_pcnt[NBLOCKS];

// exp(-t) for t >= 0 via exp2 poly on the FMA pipe (no MUFU).
// y = -t*log2(e), clamped; 2^y = 2^n * poly(r), r in [-0.5, 0.5].
__device__ __forceinline__ float exp_neg(float t) {
    const float NLOG2E = -1.4426950408889634f;
    const float MAGIC = 12582912.0f;           // 1.5 * 2^23
    float y = fmaxf(t * NLOG2E, -125.0f);
    float m = y + MAGIC;
    int ni = __float_as_int(m);
    float r = y - (m - MAGIC);                 // in [-0.5, 0.5]
    // 2^r Taylor/minimax, rel err ~4e-5
    float p = fmaf(r, 0.0096179669f, 0.0555033585f);
    p = fmaf(r, p, 0.2402264923f);
    p = fmaf(r, p, 0.6931471825f);
    p = fmaf(r, p, 1.0f);
    // scale = 2^n, n = ni - bits(MAGIC); bits = (n+127)<<23 = (ni<<23) + K (mod 2^32)
    const unsigned K = ((unsigned)(127 - 0x4B400000)) << 23;
    float sc = __int_as_float((int)(((unsigned)ni << 23) + K));
    return p * sc;
}

__global__ __launch_bounds__(TPB) void sce_main(const float* __restrict__ sim,
                                                const float* __restrict__ gt) {
    int t = blockIdx.x * TPB + threadIdx.x;
    long long base = (long long)t * VEC;
    int b = (int)(base / HW_);
    int hw = (int)(base - (long long)b * HW_);

    float4 g4 = *reinterpret_cast<const float4*>(gt + base);
    float gts[VEC] = {g4.x, g4.y, g4.z, g4.w};

    float esum[VEC], pts[VEC], ptn[VEC];
#pragma unroll
    for (int j = 0; j < VEC; ++j) { esum[j] = 0.f; pts[j] = 0.f; ptn[j] = 0.f; }

    const float* sbase = sim + (long long)b * DD * HW_ + hw;

#pragma unroll 4
    for (int d = 0; d < DD; ++d) {
        float4 s4 = *reinterpret_cast<const float4*>(sbase + (long long)d * HW_);
        float sv[VEC] = {s4.x, s4.y, s4.z, s4.w};
        float dd = 2.0f * (float)d;
#pragma unroll
        for (int j = 0; j < VEC; ++j) {
            float s = sv[j];
            esum[j] += __expf(s);                       // MUFU (lse)
            float p = exp_neg(fabsf(gts[j] - dd));      // FMA pipe (Laplace)
            pts[j] = fmaf(p, s, pts[j]);
            ptn[j] += p;
        }
    }

    double lsum = 0.0;
    unsigned int lcnt = 0u;
#pragma unroll
    for (int j = 0; j < VEC; ++j) {
        if (isfinite(gts[j])) {
            // entropy = lse - sum(Pt*s)/sum(Pt); no max-shift needed, |s| < ~7
            float ent = __logf(esum[j]) - pts[j] / ptn[j];
            lsum += (double)ent;
            lcnt++;
        }
    }

    const unsigned mask = 0xffffffffu;
#pragma unroll
    for (int o = 16; o > 0; o >>= 1) {
        lsum += __shfl_down_sync(mask, lsum, o);
        lcnt += __shfl_down_sync(mask, lcnt, o);
    }

    __shared__ double ssum[TPB / 32];
    __shared__ unsigned int scnt[TPB / 32];
    int lane = threadIdx.x & 31;
    int warp = threadIdx.x >> 5;
    if (lane == 0) { ssum[warp] = lsum; scnt[warp] = lcnt; }
    __syncthreads();

    if (warp == 0) {
        lsum = (lane < TPB / 32) ? ssum[lane] : 0.0;
        lcnt = (lane < TPB / 32) ? scnt[lane] : 0u;
#pragma unroll
        for (int o = 4; o > 0; o >>= 1) {
            lsum += __shfl_down_sync(mask, lsum, o);
            lcnt += __shfl_down_sync(mask, lcnt, o);
        }
        if (lane == 0) {
            g_part[blockIdx.x] = lsum;       // overwrite each launch: no init needed
            g_pcnt[blockIdx.x] = lcnt;
        }
    }
}

__global__ __launch_bounds__(256) void sce_fin(float* out) {
    int tid = threadIdx.x;
    double s = 0.0;
    unsigned int c = 0u;
#pragma unroll
    for (int i = tid; i < NBLOCKS; i += 256) {
        s += g_part[i];
        c += g_pcnt[i];
    }
    const unsigned mask = 0xffffffffu;
#pragma unroll
    for (int o = 16; o > 0; o >>= 1) {
        s += __shfl_down_sync(mask, s, o);
        c += __shfl_down_sync(mask, c, o);
    }
    __shared__ double ssum[8];
    __shared__ unsigned int scnt[8];
    int lane = tid & 31, warp = tid >> 5;
    if (lane == 0) { ssum[warp] = s; scnt[warp] = c; }
    __syncthreads();
    if (warp == 0) {
        s = (lane < 8) ? ssum[lane] : 0.0;
        c = (lane < 8) ? scnt[lane] : 0u;
#pragma unroll
        for (int o = 4; o > 0; o >>= 1) {
            s += __shfl_down_sync(mask, s, o);
            c += __shfl_down_sync(mask, c, o);
        }
        if (lane == 0) out[0] = (float)(s / (double)c);
    }
}

extern "C" void kernel_launch(void* const* d_in, const int* in_sizes, int n_in,
                              void* d_out, int out_size) {
    const float* sim = (const float*)d_in[0];
    const float* gt  = (const float*)d_in[1];
    float* out = (float*)d_out;

    sce_main<<<NBLOCKS, TPB>>>(sim, gt);
    sce_fin<<<1, 256>>>(out);
}

// round 3
// speedup vs baseline: 1.0333x; 1.0073x over previous
#include <cuda_runtime.h>

#define DD 64
#define H_ 256
#define W_ 512
#define HW_ (H_ * W_)
#define B_ 8
#define NPIX (B_ * HW_)
#define VEC 4
#define TPB 256
#define NTHREADS (NPIX / VEC)
#define NBLOCKS (NTHREADS / TPB)   // 1024

__device__ double g_part[NBLOCKS];
__device__ unsigned int g_pcnt[NBLOCKS];
__device__ unsigned int g_ticket;   // zero at load; last block resets to 0 each launch

__global__ __launch_bounds__(TPB) void sce_main(const float* __restrict__ sim,
                                                const float* __restrict__ gt,
                                                float* __restrict__ out) {
    int t = blockIdx.x * TPB + threadIdx.x;
    long long base = (long long)t * VEC;
    int b = (int)(base / HW_);
    int hw = (int)(base - (long long)b * HW_);

    float4 g4 = *reinterpret_cast<const float4*>(gt + base);
    float gts[VEC] = {g4.x, g4.y, g4.z, g4.w};

    const float E1  = 2.718281828459045f;    // e
    const float IE1 = 0.3678794411714423f;   // 1/e

    // Geometric recurrences: u_d = e^{(2d-gt)/2}, v_d = e^{(gt-2d)/2}
    // p_d = exp(-|gt-2d|) = min(u_d, v_d)^2.  |gt/2| <= 63 -> no overflow.
    float u[VEC], v[VEC], esum[VEC], pts[VEC], ptn[VEC];
#pragma unroll
    for (int j = 0; j < VEC; ++j) {
        float hg = 0.5f * gts[j];
        u[j] = __expf(-hg);   // gt=inf -> 0 (harmless; lane excluded later)
        v[j] = __expf(hg);    // gt=inf -> inf
        esum[j] = 0.f; pts[j] = 0.f; ptn[j] = 0.f;
    }

    const float* sbase = sim + (long long)b * DD * HW_ + hw;

#pragma unroll 4
    for (int d = 0; d < DD; ++d) {
        float4 s4 = __ldcs(reinterpret_cast<const float4*>(sbase + (long long)d * HW_));
        float sv[VEC] = {s4.x, s4.y, s4.z, s4.w};
#pragma unroll
        for (int j = 0; j < VEC; ++j) {
            float s = sv[j];
            esum[j] += __expf(s);            // lse accumulator (MUFU)
            float m = fminf(u[j], v[j]);
            float p = m * m;                 // Laplace weight, no exp
            pts[j] = fmaf(p, s, pts[j]);
            ptn[j] += p;
            u[j] *= E1;
            v[j] *= IE1;
        }
    }

    double lsum = 0.0;
    unsigned int lcnt = 0u;
#pragma unroll
    for (int j = 0; j < VEC; ++j) {
        if (isfinite(gts[j])) {
            // entropy = lse - sum(p*s)/sum(p); |s| < ~7 so no max-shift needed
            float ent = __logf(esum[j]) - pts[j] / ptn[j];
            lsum += (double)ent;
            lcnt++;
        }
    }

    const unsigned mask = 0xffffffffu;
#pragma unroll
    for (int o = 16; o > 0; o >>= 1) {
        lsum += __shfl_down_sync(mask, lsum, o);
        lcnt += __shfl_down_sync(mask, lcnt, o);
    }

    __shared__ double ssum[TPB / 32];
    __shared__ unsigned int scnt[TPB / 32];
    __shared__ int s_last;
    int lane = threadIdx.x & 31;
    int warp = threadIdx.x >> 5;
    if (lane == 0) { ssum[warp] = lsum; scnt[warp] = lcnt; }
    __syncthreads();

    if (warp == 0) {
        lsum = (lane < TPB / 32) ? ssum[lane] : 0.0;
        lcnt = (lane < TPB / 32) ? scnt[lane] : 0u;
#pragma unroll
        for (int o = 4; o > 0; o >>= 1) {
            lsum += __shfl_down_sync(mask, lsum, o);
            lcnt += __shfl_down_sync(mask, lcnt, o);
        }
        if (lane == 0) {
            g_part[blockIdx.x] = lsum;
            g_pcnt[blockIdx.x] = lcnt;
            __threadfence();
            unsigned int ticket = atomicAdd(&g_ticket, 1u);
            s_last = (ticket == NBLOCKS - 1);
        }
    }
    __syncthreads();

    // Last block to finish reduces all partials and writes the scalar.
    if (s_last) {
        int tid = threadIdx.x;
        double s = 0.0;
        unsigned int c = 0u;
#pragma unroll
        for (int i = tid; i < NBLOCKS; i += TPB) {
            s += __ldcg(&g_part[i]);          // bypass L1: written by other SMs
            c += __ldcg(&g_pcnt[i]);
        }
#pragma unroll
        for (int o = 16; o > 0; o >>= 1) {
            s += __shfl_down_sync(mask, s, o);
            c += __shfl_down_sync(mask, c, o);
        }
        __syncthreads();                      // reuse ssum/scnt safely
        if (lane == 0) { ssum[warp] = s; scnt[warp] = c; }
        __syncthreads();
        if (warp == 0) {
            s = (lane < TPB / 32) ? ssum[lane] : 0.0;
            c = (lane < TPB / 32) ? scnt[lane] : 0u;
#pragma unroll
            for (int o = 4; o > 0; o >>= 1) {
                s += __shfl_down_sync(mask, s, o);
                c += __shfl_down_sync(mask, c, o);
            }
            if (lane == 0) {
                out[0] = (float)(s / (double)c);
                g_ticket = 0u;                // reset for next graph replay
                __threadfence();
            }
        }
    }
}

extern "C" void kernel_launch(void* const* d_in, const int* in_sizes, int n_in,
                              void* d_out, int out_size) {
    const float* sim = (const float*)d_in[0];
    const float* gt  = (const float*)d_in[1];
    float* out = (float*)d_out;

    sce_main<<<NBLOCKS, TPB>>>(sim, gt, out);
}

// round 4
// speedup vs baseline: 1.1964x; 1.1578x over previous
#include <cuda_runtime.h>

#define DD 64
#define H_ 256
#define W_ 512
#define HW_ (H_ * W_)
#define B_ 8
#define NPIX (B_ * HW_)
#define VEC 4
#define TPB 128
#define NTHREADS (NPIX / VEC)          // 262144
#define NBLOCKS (NTHREADS / TPB)       // 2048

__device__ double g_part[NBLOCKS];
__device__ unsigned int g_pcnt[NBLOCKS];
__device__ unsigned int g_ticket;      // zero-init at load; last block resets each launch

__global__ __launch_bounds__(TPB, 8) void sce_main(const float* __restrict__ sim,
                                                   const float* __restrict__ gt,
                                                   float* __restrict__ out) {
    int t = blockIdx.x * TPB + threadIdx.x;
    long long base = (long long)t * VEC;
    int b = (int)(base / HW_);
    int hw = (int)(base - (long long)b * HW_);

    float4 g4 = *reinterpret_cast<const float4*>(gt + base);
    float gts[VEC] = {g4.x, g4.y, g4.z, g4.w};

    const float E1     = 2.718281828459045f;     // e
    const float IE1    = 0.3678794411714423f;    // 1/e
    const float EXPM64 = 1.6038108905486378e-28f;// e^-64
    const float C1     = 0.15651764274966565f;   // 1/(e^2-1)
    const float C2     = 1.1565176427496657f;    // 1/(1-e^-2)

    // u_d = e^{(2d-gt)/2}, v_d = e^{(gt-2d)/2}; p_d = exp(-|gt-2d|) = min(u,v)^2
    float u[VEC], v[VEC], esum[VEC], pts[VEC];
#pragma unroll
    for (int j = 0; j < VEC; ++j) {
        float hg = 0.5f * gts[j];
        u[j] = __expf(-hg);
        v[j] = __expf(hg);
        esum[j] = 0.f; pts[j] = 0.f;
    }

    const float* sbase = sim + (long long)b * DD * HW_ + hw;

    auto body = [&](float4 s4) {
        float sv[VEC] = {s4.x, s4.y, s4.z, s4.w};
#pragma unroll
        for (int j = 0; j < VEC; ++j) {
            float s = sv[j];
            esum[j] += __expf(s);
            float mm = fminf(u[j], v[j]);
            pts[j] = fmaf(mm * mm, s, pts[j]);
            u[j] *= E1;
            v[j] *= IE1;
        }
    };

    // Software-pipelined: prefetch next 4 planes while computing current 4.
    float4 buf[4], nxt[4];
#pragma unroll
    for (int k = 0; k < 4; ++k)
        buf[k] = __ldcs(reinterpret_cast<const float4*>(sbase + (long long)k * HW_));

#pragma unroll 1
    for (int db = 0; db < DD - 4; db += 4) {
#pragma unroll
        for (int k = 0; k < 4; ++k)
            nxt[k] = __ldcs(reinterpret_cast<const float4*>(sbase + (long long)(db + 4 + k) * HW_));
#pragma unroll
        for (int k = 0; k < 4; ++k) body(buf[k]);
#pragma unroll
        for (int k = 0; k < 4; ++k) buf[k] = nxt[k];
    }
#pragma unroll
    for (int k = 0; k < 4; ++k) body(buf[k]);

    double lsum = 0.0;
    unsigned int lcnt = 0u;
#pragma unroll
    for (int j = 0; j < VEC; ++j) {
        if (isfinite(gts[j])) {
            // Closed-form sum of Laplace weights (two geometric series):
            // t = gt - 2*floor(gt/2);  e^{-gt} = (u_f * e^-64)^2;  e^{gt-128} = v_f^2
            float gtv = gts[j];
            float m0 = floorf(gtv * 0.5f);
            float tt = fmaf(-2.0f, m0, gtv);          // [0, 2)
            float et2 = __expf(tt - 2.0f);            // e^{t-2}
            float e2t = 1.0f / et2;                   // e^{2-t}
            float u0s = u[j] * EXPM64; u0s *= u0s;    // e^{-gt}
            float wsq = v[j] * v[j];                  // e^{gt-128}
            float ptn = (e2t - u0s) * C1 + (et2 - wsq) * C2;
            float ent = __logf(esum[j]) - pts[j] / ptn;
            lsum += (double)ent;
            lcnt++;
        }
    }

    const unsigned mask = 0xffffffffu;
#pragma unroll
    for (int o = 16; o > 0; o >>= 1) {
        lsum += __shfl_down_sync(mask, lsum, o);
        lcnt += __shfl_down_sync(mask, lcnt, o);
    }

    __shared__ double ssum[TPB / 32];
    __shared__ unsigned int scnt[TPB / 32];
    __shared__ int s_last;
    int lane = threadIdx.x & 31;
    int warp = threadIdx.x >> 5;
    if (lane == 0) { ssum[warp] = lsum; scnt[warp] = lcnt; }
    __syncthreads();

    if (warp == 0) {
        lsum = (lane < TPB / 32) ? ssum[lane] : 0.0;
        lcnt = (lane < TPB / 32) ? scnt[lane] : 0u;
#pragma unroll
        for (int o = 2; o > 0; o >>= 1) {
            lsum += __shfl_down_sync(mask, lsum, o);
            lcnt += __shfl_down_sync(mask, lcnt, o);
        }
        if (lane == 0) {
            g_part[blockIdx.x] = lsum;
            g_pcnt[blockIdx.x] = lcnt;
            __threadfence();
            unsigned int ticket = atomicAdd(&g_ticket, 1u);
            s_last = (ticket == NBLOCKS - 1);
        }
    }
    __syncthreads();

    if (s_last) {
        int tid = threadIdx.x;
        double s = 0.0;
        unsigned int c = 0u;
#pragma unroll
        for (int i = tid; i < NBLOCKS; i += TPB) {
            s += __ldcg(&g_part[i]);
            c += __ldcg(&g_pcnt[i]);
        }
#pragma unroll
        for (int o = 16; o > 0; o >>= 1) {
            s += __shfl_down_sync(mask, s, o);
            c += __shfl_down_sync(mask, c, o);
        }
        __syncthreads();
        if (lane == 0) { ssum[warp] = s; scnt[warp] = c; }
        __syncthreads();
        if (warp == 0) {
            s = (lane < TPB / 32) ? ssum[lane] : 0.0;
            c = (lane < TPB / 32) ? scnt[lane] : 0u;
#pragma unroll
            for (int o = 2; o > 0; o >>= 1) {
                s += __shfl_down_sync(mask, s, o);
                c += __shfl_down_sync(mask, c, o);
            }
            if (lane == 0) {
                out[0] = (float)(s / (double)c);
                g_ticket = 0u;
                __threadfence();
            }
        }
    }
}

extern "C" void kernel_launch(void* const* d_in, const int* in_sizes, int n_in,
                              void* d_out, int out_size) {
    const float* sim = (const float*)d_in[0];
    const float* gt  = (const float*)d_in[1];
    float* out = (float*)d_out;

    sce_main<<<NBLOCKS, TPB>>>(sim, gt, out);
}